// round 6
// baseline (speedup 1.0000x reference)
#include <cuda_runtime.h>
#include <cstdint>

// QuantumLSTM v4: phase-split.
// Phase 1: Z[T*B,64] = X @ Wx^T (all 4 gates' input-GEMV hoisted out of the
//          recurrence). FFMA2-tiled GEMM, fma-bound.
// Phase 2: warp-per-row recurrence. lane = gate*8 + l, owns units {2l,2l+1}.
//          No barriers, no smem: h-GEMV + scan + gate exchange all via shfl.

namespace {
constexpr int TT = 1024;
constexpr int BB = 1024;
constexpr int INDIM = 128;
constexpr int HH = 16;
constexpr int DD = 144;
constexpr int NOUT = 64;          // 4 gates x 16 units
constexpr size_t NROW = (size_t)TT * BB;

typedef unsigned long long ull;

__device__ __forceinline__ void ffma2(ull &acc, ull a, ull b) {
    asm("fma.rn.f32x2 %0, %1, %2, %0;" : "+l"(acc) : "l"(a), "l"(b));
}
__device__ __forceinline__ ull packf2(float lo, float hi) {
    ull r;
    asm("mov.b64 %0, {%1, %2};" : "=l"(r) : "f"(lo), "f"(hi));
    return r;
}
__device__ __forceinline__ float2 unpackf2(ull v) {
    float lo, hi;
    asm("mov.b64 {%0, %1}, %2;" : "=f"(lo), "=f"(hi) : "l"(v));
    return make_float2(lo, hi);
}
__device__ __forceinline__ float tanh_f(float x) {
    float u = __expf(-2.0f * x);
    return __fdividef(1.0f - u, 1.0f + u);
}
__device__ __forceinline__ void cp_async16(uint32_t saddr, const float* g) {
    asm volatile("cp.async.ca.shared.global [%0], [%1], 16;" :: "r"(saddr), "l"(g));
}
}  // namespace

// 256 MB scratch for Z (allowed: __device__ global array).
__device__ float g_Z[NROW * NOUT];

// ---------------------------------------------------------------------------
// Phase 1: Z = X @ Wx^T.  M-tile 64 rows, N = 64 cols, K = 128 in 2 chunks.
// Block 256 thr: ri = tid>>5 (8 rows 8ri..8ri+7), ci = tid&31 (cols 2ci,2ci+1).
// x LDS.128 is a full-warp broadcast (all lanes share ri).
// ---------------------------------------------------------------------------
__global__ __launch_bounds__(256, 2) void p1_gemm(
    const float* __restrict__ X,
    const float* __restrict__ Wf, const float* __restrict__ Wi,
    const float* __restrict__ Wg, const float* __restrict__ Wo,
    float* __restrict__ Z)
{
    constexpr int WPITCH = 132;   // floats; 528B rows (16B aligned, banks spread)
    constexpr int XPITCH = 68;    // floats; 272B rows
    __shared__ __align__(16) float Wt[NOUT][WPITCH];
    __shared__ __align__(16) float Xt[2][64][XPITCH];

    const int tid = threadIdx.x;
    const int ci  = tid & 31;
    const int ri  = tid >> 5;
    const size_t rowBase = (size_t)blockIdx.x * 64;

    // ---- W -> smem (once): row c = gate*16+u, cols 0..127 ----
    {
        int c = tid >> 2, seg = tid & 3;  // 32 floats per thread
        const float* Wsrc = (c < 16) ? Wf : (c < 32) ? Wi : (c < 48) ? Wg : Wo;
        const float* src = Wsrc + (c & 15) * DD + seg * 32;
        float* dst = &Wt[c][seg * 32];
        #pragma unroll
        for (int i = 0; i < 8; ++i)
            *reinterpret_cast<float4*>(dst + i * 4) =
                *reinterpret_cast<const float4*>(src + i * 4);
    }

    // ---- X chunk staging: row = tid>>2, 16-float segment = tid&3 ----
    const int xr = tid >> 2, xs = tid & 3;
    const float* xg = X + (rowBase + xr) * INDIM + xs * 16;
    uint32_t xsm[2];
    xsm[0] = (uint32_t)__cvta_generic_to_shared(&Xt[0][xr][xs * 16]);
    xsm[1] = (uint32_t)__cvta_generic_to_shared(&Xt[1][xr][xs * 16]);

    #pragma unroll
    for (int i = 0; i < 4; ++i) cp_async16(xsm[0] + i * 16, xg + i * 4);
    asm volatile("cp.async.commit_group;");
    asm volatile("cp.async.wait_group 0;");
    __syncthreads();

    ull acc[8][2];
    #pragma unroll
    for (int j = 0; j < 8; ++j) { acc[j][0] = 0ull; acc[j][1] = 0ull; }

    #pragma unroll
    for (int ch = 0; ch < 2; ++ch) {
        if (ch == 0) {  // prefetch chunk 1 (k = 64..127)
            #pragma unroll
            for (int i = 0; i < 4; ++i) cp_async16(xsm[1] + i * 16, xg + 64 + i * 4);
            asm volatile("cp.async.commit_group;");
        }
        const int kbase = ch * 64;
        #pragma unroll
        for (int q = 0; q < 16; ++q) {        // k-quads within chunk
            longlong2 w0 = *reinterpret_cast<const longlong2*>(&Wt[2 * ci][kbase + q * 4]);
            longlong2 w1 = *reinterpret_cast<const longlong2*>(&Wt[2 * ci + 1][kbase + q * 4]);
            #pragma unroll
            for (int j = 0; j < 8; ++j) {
                longlong2 xv = *reinterpret_cast<const longlong2*>(&Xt[ch][8 * ri + j][q * 4]);
                ffma2(acc[j][0], (ull)xv.x, (ull)w0.x);
                ffma2(acc[j][0], (ull)xv.y, (ull)w0.y);
                ffma2(acc[j][1], (ull)xv.x, (ull)w1.x);
                ffma2(acc[j][1], (ull)xv.y, (ull)w1.y);
            }
        }
        if (ch == 0) {
            asm volatile("cp.async.wait_group 0;");
            __syncthreads();
        }
    }

    // ---- epilogue: pairwise reduce + coalesced float2 stores ----
    #pragma unroll
    for (int j = 0; j < 8; ++j) {
        float2 a = unpackf2(acc[j][0]);
        float2 b = unpackf2(acc[j][1]);
        float2 z = make_float2(a.x + a.y, b.x + b.y);
        *reinterpret_cast<float2*>(Z + (rowBase + 8 * ri + j) * NOUT + 2 * ci) = z;
    }
}

// ---------------------------------------------------------------------------
// Phase 2: recurrence. One warp per batch row; lane = g*8+l owns units
// {2l, 2l+1} of gate g. h/c replicated across the 4 gate groups.
// ---------------------------------------------------------------------------
__global__ __launch_bounds__(128, 8) void p2_rec(
    const float* __restrict__ Z,
    const float* __restrict__ Wf, const float* __restrict__ bf, const float* __restrict__ thf,
    const float* __restrict__ Wi, const float* __restrict__ bi, const float* __restrict__ thi,
    const float* __restrict__ Wg, const float* __restrict__ bg, const float* __restrict__ thg,
    const float* __restrict__ Wo, const float* __restrict__ bo, const float* __restrict__ tho,
    float* __restrict__ out)
{
    const int tid  = threadIdx.x;
    const int lane = tid & 31;
    const int warp = tid >> 5;
    const int g    = lane >> 3;       // gate
    const int l    = lane & 7;        // unit-pair index
    const int u0   = 2 * l, u1 = 2 * l + 1;
    const int row  = blockIdx.x * 4 + warp;
    const unsigned FULL = 0xffffffffu;

    const float* Wsel = (g == 0) ? Wf : (g == 1) ? Wi : (g == 2) ? Wg : Wo;
    const float* bsel = (g == 0) ? bf : (g == 1) ? bi : (g == 2) ? bg : bo;
    const float* tsel = (g == 0) ? thf : (g == 1) ? thi : (g == 2) ? thg : tho;
    const float cth0 = bsel[u0] + tsel[u0];   // sin(z + b + theta): fold constants
    const float cth1 = bsel[u1] + tsel[u1];

    // Recurrent weights, interleaved over the unit pair: wh[j] = {W[u0][128+j], W[u1][128+j]}
    ull wh[HH];
    #pragma unroll
    for (int j = 0; j < HH; ++j)
        wh[j] = packf2(Wsel[u0 * DD + INDIM + j], Wsel[u1 * DD + INDIM + j]);

    const float* zp = Z + (size_t)row * NOUT + g * 16 + u0;
    const size_t zstep = (size_t)BB * NOUT;
    float2 zbuf[2];
    zbuf[0] = *reinterpret_cast<const float2*>(zp);
    zbuf[1] = *reinterpret_cast<const float2*>(zp + zstep);

    float h0 = 0.f, h1 = 0.f, c0 = 0.f, c1 = 0.f;
    float* outp = out + (size_t)row * HH + u0;
    const float qscale = (g == 2) ? 2.0f : 1.0f;   // tanh(q) = 2*sigmoid(2q)-1

    for (int t = 0; t < TT; ++t) {
        float2 zx = zbuf[t & 1];
        if (t + 2 < TT)   // distance-2 prefetch: LDG ~600cyc > step chain
            zbuf[t & 1] = *reinterpret_cast<const float2*>(zp + (size_t)(t + 2) * zstep);

        // ---- z += h . Wh (h gathered in-group via shfl) ----
        ull zacc = packf2(zx.x, zx.y);
        ull hp = packf2(h0, h1);
        #pragma unroll
        for (int jj = 0; jj < 8; ++jj) {
            ull hj = __shfl_sync(FULL, hp, (lane & 24) | jj);
            float2 hf = unpackf2(hj);
            ffma2(zacc, packf2(hf.x, hf.x), wh[2 * jj]);
            ffma2(zacc, packf2(hf.y, hf.y), wh[2 * jj + 1]);
        }
        float2 zf = unpackf2(zacc);

        // ---- qgate: sin then cumsum over 16 units (2/lane, 8-lane segments) ----
        float s0 = __sinf(zf.x + cth0);
        float s1 = __sinf(zf.y + cth1);
        float ps = s0 + s1;
        #pragma unroll
        for (int d = 1; d < 8; d <<= 1) {
            float v = __shfl_up_sync(FULL, ps, d, 8);   // width=8 segments
            if (l >= d) ps += v;
        }
        float total = __shfl_sync(FULL, ps, lane | 7);  // segment total
        float cum1 = ps;
        float cum0 = ps - s1;
        float q0 = (l == 0) ? (s0 + total) : cum0;
        float q1 = cum1;

        // ---- branchless activation: sigmoid, or tanh via 2*sig(2q)-1 ----
        float e0 = __expf(-q0 * qscale), e1 = __expf(-q1 * qscale);
        float sg0 = __fdividef(1.0f, 1.0f + e0);
        float sg1 = __fdividef(1.0f, 1.0f + e1);
        float a0 = (g == 2) ? (2.0f * sg0 - 1.0f) : sg0;
        float a1 = (g == 2) ? (2.0f * sg1 - 1.0f) : sg1;

        // ---- gather all 4 gates for units (u0,u1) ----
        ull ap = packf2(a0, a1);
        ull fp_ = __shfl_sync(FULL, ap, l);
        ull ip_ = __shfl_sync(FULL, ap, 8 | l);
        ull gp_ = __shfl_sync(FULL, ap, 16 | l);
        ull op_ = __shfl_sync(FULL, ap, 24 | l);
        float2 fv = unpackf2(fp_), iv = unpackf2(ip_);
        float2 gv = unpackf2(gp_), ov = unpackf2(op_);

        c0 = fv.x * c0 + iv.x * gv.x;
        c1 = fv.y * c1 + iv.y * gv.y;
        h0 = ov.x * tanh_f(c0);
        h1 = ov.y * tanh_f(c1);

        if (g == 0)
            *reinterpret_cast<float2*>(outp + (size_t)t * BB * HH) = make_float2(h0, h1);
    }

    if (g == 0) {
        size_t base = (size_t)TT * BB * HH;
        *reinterpret_cast<float2*>(out + base + (size_t)row * HH + u0) = make_float2(h0, h1);
        *reinterpret_cast<float2*>(out + base + (size_t)BB * HH + (size_t)row * HH + u0) = make_float2(c0, c1);
    }
}

extern "C" void kernel_launch(void* const* d_in, const int* in_sizes, int n_in,
                              void* d_out, int out_size) {
    (void)in_sizes; (void)n_in; (void)out_size;
    const float* X   = (const float*)d_in[0];
    const float* Wf  = (const float*)d_in[1];
    const float* bf  = (const float*)d_in[2];
    const float* thf = (const float*)d_in[3];
    const float* Wi  = (const float*)d_in[4];
    const float* bi  = (const float*)d_in[5];
    const float* thi = (const float*)d_in[6];
    const float* Wg  = (const float*)d_in[7];
    const float* bg  = (const float*)d_in[8];
    const float* thg = (const float*)d_in[9];
    const float* Wo  = (const float*)d_in[10];
    const float* bo  = (const float*)d_in[11];
    const float* tho = (const float*)d_in[12];
    float* out = (float*)d_out;

    float* Zp = nullptr;
    cudaGetSymbolAddress((void**)&Zp, g_Z);   // no allocation; host-side lookup

    p1_gemm<<<(int)(NROW / 64), 256>>>(X, Wf, Wi, Wg, Wo, Zp);
    p2_rec<<<BB / 4, 128>>>(Zp, Wf, bf, thf, Wi, bi, thi,
                            Wg, bg, thg, Wo, bo, tho, out);
}

// round 7
// speedup vs baseline: 1.3742x; 1.3742x over previous
#include <cuda_runtime.h>
#include <cstdint>

// QuantumLSTM v5: phase-split, both phases repaired per R6 ncu.
// p1: Z[T*B,64] = X @ Wx^T. Persistent-ish: 1024 blocks x 16 tiles, W staged
//     once per block (swizzled, conflict-free), continuous cp.async pipeline.
// p2: warp-per-row recurrence, branch-free loop body (predicated store via asm,
//     clamped ring-4 Z prefetch), split ffma2 chains, concurrent scan+reduce.

namespace {
constexpr int TT = 1024;
constexpr int BB = 1024;
constexpr int INDIM = 128;
constexpr int HH = 16;
constexpr int DD = 144;
constexpr int NOUT = 64;
constexpr size_t NROW = (size_t)TT * BB;
constexpr int TPB = 16;                         // row-tiles per p1 block
constexpr int P1_BLOCKS = (int)(NROW / 64 / TPB); // 1024
constexpr int XPITCH = 68;

typedef unsigned long long ull;

__device__ __forceinline__ void ffma2(ull &acc, ull a, ull b) {
    asm("fma.rn.f32x2 %0, %1, %2, %0;" : "+l"(acc) : "l"(a), "l"(b));
}
__device__ __forceinline__ ull addf2(ull a, ull b) {
    ull r; asm("add.rn.f32x2 %0, %1, %2;" : "=l"(r) : "l"(a), "l"(b)); return r;
}
__device__ __forceinline__ ull packf2(float lo, float hi) {
    ull r; asm("mov.b64 %0, {%1, %2};" : "=l"(r) : "f"(lo), "f"(hi)); return r;
}
__device__ __forceinline__ float2 unpackf2(ull v) {
    float lo, hi; asm("mov.b64 {%0, %1}, %2;" : "=f"(lo), "=f"(hi) : "l"(v));
    return make_float2(lo, hi);
}
__device__ __forceinline__ float tanh_f(float x) {
    float u = __expf(-2.0f * x);
    return __fdividef(1.0f - u, 1.0f + u);
}
__device__ __forceinline__ void cp_async16(uint32_t saddr, const float* g) {
    asm volatile("cp.async.ca.shared.global [%0], [%1], 16;" :: "r"(saddr), "l"(g));
}
}  // namespace

__device__ float g_Z[NROW * NOUT];   // 256 MB scratch

// ---------------------------------------------------------------------------
// Phase 1
// ---------------------------------------------------------------------------
__global__ __launch_bounds__(256, 2) void p1_gemm(
    const float* __restrict__ X,
    const float* __restrict__ Wf, const float* __restrict__ Wi,
    const float* __restrict__ Wg, const float* __restrict__ Wo,
    float* __restrict__ Z)
{
    __shared__ __align__(16) float Wt[64 * 128];        // swizzled, 32 KB
    __shared__ __align__(16) float Xt[2][64][XPITCH];   // 34.8 KB

    const int tid = threadIdx.x;
    const int ci  = tid & 31;
    const int ri  = tid >> 5;

    // ---- W staging, once per block, quad-XOR swizzle phys = quad ^ ((c>>1)&7) ----
    {
        int c = tid >> 2, seg = tid & 3;
        const float* Wsrc = (c < 16) ? Wf : (c < 32) ? Wi : (c < 48) ? Wg : Wo;
        const float* src = Wsrc + (c & 15) * DD + seg * 32;
        int sw = (c >> 1) & 7;
        #pragma unroll
        for (int i = 0; i < 8; ++i) {
            int phys = (seg * 8 + i) ^ sw;
            *reinterpret_cast<float4*>(&Wt[c * 128 + phys * 4]) =
                *reinterpret_cast<const float4*>(src + i * 4);
        }
    }

    // ---- X chunk staging map ----
    const int xr = tid >> 2, xs = tid & 3;
    uint32_t xsm[2];
    xsm[0] = (uint32_t)__cvta_generic_to_shared(&Xt[0][xr][xs * 16]);
    xsm[1] = (uint32_t)__cvta_generic_to_shared(&Xt[1][xr][xs * 16]);
    const size_t blockRow0 = (size_t)blockIdx.x * (TPB * 64);
    const float* xbase = X + (blockRow0 + xr) * INDIM + xs * 16;
    // chunk g covers rows (g>>1)*64, k-offset (g&1)*64

    {   // chunk 0
        const float* p = xbase;
        #pragma unroll
        for (int i = 0; i < 4; ++i) cp_async16(xsm[0] + i * 16, p + i * 4);
        asm volatile("cp.async.commit_group;");
        asm volatile("cp.async.wait_group 0;");
    }
    __syncthreads();

    const float* wp0 = &Wt[(2 * ci) * 128];
    const float* wp1 = &Wt[(2 * ci + 1) * 128];
    const int swr = ci & 7;

    ull acc[8][2];
    #pragma unroll
    for (int j = 0; j < 8; ++j) { acc[j][0] = 0ull; acc[j][1] = 0ull; }

    for (int g = 0; g < TPB * 2; ++g) {
        const int buf = g & 1;
        if (g + 1 < TPB * 2) {
            int gn = g + 1;
            const float* p = xbase + (size_t)(gn >> 1) * (64 * INDIM) + (gn & 1) * 64;
            #pragma unroll
            for (int i = 0; i < 4; ++i) cp_async16(xsm[buf ^ 1] + i * 16, p + i * 4);
            asm volatile("cp.async.commit_group;");
        }
        const int qbase = (g & 1) * 16;
        #pragma unroll
        for (int q = 0; q < 16; ++q) {
            int phys4 = ((qbase + q) ^ swr) * 4;
            longlong2 w0 = *reinterpret_cast<const longlong2*>(wp0 + phys4);
            longlong2 w1 = *reinterpret_cast<const longlong2*>(wp1 + phys4);
            #pragma unroll
            for (int j = 0; j < 8; ++j) {
                longlong2 xv = *reinterpret_cast<const longlong2*>(&Xt[buf][8 * ri + j][q * 4]);
                ffma2(acc[j][0], (ull)xv.x, (ull)w0.x);
                ffma2(acc[j][0], (ull)xv.y, (ull)w0.y);
                ffma2(acc[j][1], (ull)xv.x, (ull)w1.x);
                ffma2(acc[j][1], (ull)xv.y, (ull)w1.y);
            }
        }
        asm volatile("cp.async.wait_group 0;");
        __syncthreads();
        if (g & 1) {   // row-tile complete: epilogue + reset
            size_t rb = blockRow0 + (size_t)(g >> 1) * 64;
            #pragma unroll
            for (int j = 0; j < 8; ++j) {
                float2 a = unpackf2(acc[j][0]);
                float2 b = unpackf2(acc[j][1]);
                *reinterpret_cast<float2*>(Z + (rb + 8 * ri + j) * NOUT + 2 * ci) =
                    make_float2(a.x + a.y, b.x + b.y);
                acc[j][0] = 0ull; acc[j][1] = 0ull;
            }
        }
    }
}

// ---------------------------------------------------------------------------
// Phase 2: warp-per-row recurrence, branch-free body.
// lane = g*8 + l, owns units {2l, 2l+1} of gate g.
// ---------------------------------------------------------------------------
__global__ __launch_bounds__(128, 8) void p2_rec(
    const float* __restrict__ Z,
    const float* __restrict__ Wf, const float* __restrict__ bf, const float* __restrict__ thf,
    const float* __restrict__ Wi, const float* __restrict__ bi, const float* __restrict__ thi,
    const float* __restrict__ Wg, const float* __restrict__ bg, const float* __restrict__ thg,
    const float* __restrict__ Wo, const float* __restrict__ bo, const float* __restrict__ tho,
    float* __restrict__ out)
{
    const int tid  = threadIdx.x;
    const int lane = tid & 31;
    const int warp = tid >> 5;
    const int g    = lane >> 3;
    const int l    = lane & 7;
    const int u0   = 2 * l, u1 = 2 * l + 1;
    const int row  = blockIdx.x * 4 + warp;
    const int hsrc = lane & 24;           // own-group base for h gathers
    const unsigned FULL = 0xffffffffu;

    const float* Wsel = (g == 0) ? Wf : (g == 1) ? Wi : (g == 2) ? Wg : Wo;
    const float* bsel = (g == 0) ? bf : (g == 1) ? bi : (g == 2) ? bg : bo;
    const float* tsel = (g == 0) ? thf : (g == 1) ? thi : (g == 2) ? thg : tho;
    const float cth0 = bsel[u0] + tsel[u0];
    const float cth1 = bsel[u1] + tsel[u1];
    const float nqs  = (g == 2) ? -2.0f : -1.0f;   // exp(nqs * q)
    const float sc2  = (g == 2) ?  2.0f :  1.0f;   // act = sc2*sig + off2
    const float off2 = (g == 2) ? -1.0f :  0.0f;

    ull wh[HH];
    #pragma unroll
    for (int j = 0; j < HH; ++j)
        wh[j] = packf2(Wsel[u0 * DD + INDIM + j], Wsel[u1 * DD + INDIM + j]);

    const float* zp = Z + (size_t)row * NOUT + g * 16 + u0;
    const size_t zstep = (size_t)BB * NOUT;

    // ring-4 prefetch
    float2 zbuf[4];
    #pragma unroll
    for (int i = 0; i < 4; ++i)
        zbuf[i] = *reinterpret_cast<const float2*>(zp + (size_t)i * zstep);

    float h0 = 0.f, h1 = 0.f, c0 = 0.f, c1 = 0.f;
    float* outp = out + (size_t)row * HH + u0;

    #pragma unroll 2
    for (int t = 0; t < TT; ++t) {
        float2 zx = zbuf[t & 3];
        int tp = (t + 4 < TT) ? (t + 4) : (TT - 1);        // selp, no branch
        zbuf[t & 3] = *reinterpret_cast<const float2*>(zp + (size_t)tp * zstep);

        // ---- z += h . Wh : two independent ffma2 chains ----
        ull z1 = packf2(zx.x, zx.y), z2 = 0ull;
        ull hp = packf2(h0, h1);
        #pragma unroll
        for (int jj = 0; jj < 4; ++jj) {
            ull hj = __shfl_sync(FULL, hp, hsrc | jj);
            float2 hf = unpackf2(hj);
            ffma2(z1, packf2(hf.x, hf.x), wh[2 * jj]);
            ffma2(z1, packf2(hf.y, hf.y), wh[2 * jj + 1]);
        }
        #pragma unroll
        for (int jj = 4; jj < 8; ++jj) {
            ull hj = __shfl_sync(FULL, hp, hsrc | jj);
            float2 hf = unpackf2(hj);
            ffma2(z2, packf2(hf.x, hf.x), wh[2 * jj]);
            ffma2(z2, packf2(hf.y, hf.y), wh[2 * jj + 1]);
        }
        float2 zf = unpackf2(addf2(z1, z2));

        // ---- qgate: sin, then prefix scan + segment total concurrently ----
        float s0 = __sinf(zf.x + cth0);
        float s1 = __sinf(zf.y + cth1);
        float s01 = s0 + s1;
        float ps = s01, tt_ = s01;
        #pragma unroll
        for (int d = 1; d < 8; d <<= 1) {
            float v = __shfl_up_sync(FULL, ps, d, 8);
            ps += (l >= d) ? v : 0.0f;
            tt_ += __shfl_xor_sync(FULL, tt_, d, 8);
        }
        float cum1 = ps;
        float cum0 = ps - s1;
        float q0 = (l == 0) ? (s0 + tt_) : cum0;
        float q1 = cum1;

        // ---- activation: sigmoid or tanh via sc2*sig+off2 (branchless) ----
        float e0 = __expf(q0 * nqs), e1 = __expf(q1 * nqs);
        float sg0 = __fdividef(1.0f, 1.0f + e0);
        float sg1 = __fdividef(1.0f, 1.0f + e1);
        float a0 = fmaf(sc2, sg0, off2);
        float a1 = fmaf(sc2, sg1, off2);

        // ---- gather gates for units (u0,u1) ----
        ull ap = packf2(a0, a1);
        ull fp_ = __shfl_sync(FULL, ap, l);
        ull ip_ = __shfl_sync(FULL, ap, 8 | l);
        ull gp_ = __shfl_sync(FULL, ap, 16 | l);
        ull op_ = __shfl_sync(FULL, ap, 24 | l);
        float2 fv = unpackf2(fp_), iv = unpackf2(ip_);
        float2 gv = unpackf2(gp_), ov = unpackf2(op_);

        c0 = fmaf(fv.x, c0, iv.x * gv.x);
        c1 = fmaf(fv.y, c1, iv.y * gv.y);
        h0 = ov.x * tanh_f(c0);
        h1 = ov.y * tanh_f(c1);

        // predicated store (no BSSY): only g==0 lanes write
        float* sp = outp + (size_t)t * (BB * HH);
        asm volatile(
            "{ .reg .pred p; setp.eq.s32 p, %0, 0;\n\t"
            "@p st.global.v2.f32 [%1], {%2, %3}; }"
            :: "r"(g), "l"(sp), "f"(h0), "f"(h1) : "memory");
    }

    if (g == 0) {
        size_t base = (size_t)TT * BB * HH;
        *reinterpret_cast<float2*>(out + base + (size_t)row * HH + u0) = make_float2(h0, h1);
        *reinterpret_cast<float2*>(out + base + (size_t)BB * HH + (size_t)row * HH + u0) = make_float2(c0, c1);
    }
}

extern "C" void kernel_launch(void* const* d_in, const int* in_sizes, int n_in,
                              void* d_out, int out_size) {
    (void)in_sizes; (void)n_in; (void)out_size;
    const float* X   = (const float*)d_in[0];
    const float* Wf  = (const float*)d_in[1];
    const float* bf  = (const float*)d_in[2];
    const float* thf = (const float*)d_in[3];
    const float* Wi  = (const float*)d_in[4];
    const float* bi  = (const float*)d_in[5];
    const float* thi = (const float*)d_in[6];
    const float* Wg  = (const float*)d_in[7];
    const float* bg  = (const float*)d_in[8];
    const float* thg = (const float*)d_in[9];
    const float* Wo  = (const float*)d_in[10];
    const float* bo  = (const float*)d_in[11];
    const float* tho = (const float*)d_in[12];
    float* out = (float*)d_out;

    float* Zp = nullptr;
    cudaGetSymbolAddress((void**)&Zp, g_Z);

    p1_gemm<<<P1_BLOCKS, 256>>>(X, Wf, Wi, Wg, Wo, Zp);
    p2_rec<<<BB / 4, 128>>>(Zp, Wf, bf, thf, Wi, bi, thi,
                            Wg, bg, thg, Wo, bo, tho, out);
}

// round 12
// speedup vs baseline: 1.5180x; 1.1046x over previous
#include <cuda_runtime.h>
#include <cstdint>

// QuantumLSTM v6.
// p1: Z = X @ Wx^T with W register-stationary (64 f32x2 regs = one full-K
//     column per lane). X tile broadcast from smem; no W shared-mem traffic.
//     Block 256thr = 8 warps = (4 row-groups x 2 col-halves); 32 rows x 64
//     cols per tile, 32 tiles per block, grid 1024.
// p2: warp-per-row recurrence. R7 bug fixed: no 64-reg cap (was spilling
//     wh/zbuf to local), unroll 4 so the prefetch ring index is static.

namespace {
constexpr int TT = 1024;
constexpr int BB = 1024;
constexpr int INDIM = 128;
constexpr int HH = 16;
constexpr int DD = 144;
constexpr int NOUT = 64;
constexpr size_t NROW = (size_t)TT * BB;
constexpr int ROWS_PER_TILE = 32;
constexpr int TILES_PER_BLOCK = 32;
constexpr int P1_BLOCKS = (int)(NROW / (ROWS_PER_TILE * TILES_PER_BLOCK)); // 1024

typedef unsigned long long ull;

__device__ __forceinline__ void ffma2(ull &acc, ull a, ull b) {
    asm("fma.rn.f32x2 %0, %1, %2, %0;" : "+l"(acc) : "l"(a), "l"(b));
}
__device__ __forceinline__ ull addf2(ull a, ull b) {
    ull r; asm("add.rn.f32x2 %0, %1, %2;" : "=l"(r) : "l"(a), "l"(b)); return r;
}
__device__ __forceinline__ ull packf2(float lo, float hi) {
    ull r; asm("mov.b64 %0, {%1, %2};" : "=l"(r) : "f"(lo), "f"(hi)); return r;
}
__device__ __forceinline__ float2 unpackf2(ull v) {
    float lo, hi; asm("mov.b64 {%0, %1}, %2;" : "=f"(lo), "=f"(hi) : "l"(v));
    return make_float2(lo, hi);
}
__device__ __forceinline__ float tanh_f(float x) {
    float u = __expf(-2.0f * x);
    return __fdividef(1.0f - u, 1.0f + u);
}
__device__ __forceinline__ void cp_async16(uint32_t saddr, const float* g) {
    asm volatile("cp.async.ca.shared.global [%0], [%1], 16;" :: "r"(saddr), "l"(g));
}
}  // namespace

__device__ float g_Z[NROW * NOUT];   // 256 MB scratch

// ---------------------------------------------------------------------------
// Phase 1: Z[T*B,64] = X @ Wx^T, weight-stationary in registers.
// ---------------------------------------------------------------------------
__global__ __launch_bounds__(256, 1) void p1_gemm(
    const float* __restrict__ X,
    const float* __restrict__ Wf, const float* __restrict__ Wi,
    const float* __restrict__ Wg, const float* __restrict__ Wo,
    float* __restrict__ Z)
{
    __shared__ __align__(16) float Xt[2][ROWS_PER_TILE][INDIM];  // 32 KB

    const int tid  = threadIdx.x;
    const int lane = tid & 31;
    const int warp = tid >> 5;
    const int rg   = warp & 3;     // row group: rows 8*rg..8*rg+7
    const int ch   = warp >> 2;    // col half: cols ch*32 + lane
    const int col  = ch * 32 + lane;

    // ---- W column (full K=128) -> 64 packed f32x2 registers ----
    const float* Wsrc = (col < 16) ? Wf : (col < 32) ? Wi : (col < 48) ? Wg : Wo;
    const float* wrow = Wsrc + (col & 15) * DD;      // 576B offset: 16B aligned
    ull wreg[INDIM / 2];
    #pragma unroll
    for (int m = 0; m < INDIM / 4; ++m) {            // 32 x float4
        longlong2 v = reinterpret_cast<const longlong2*>(wrow)[m];
        wreg[2 * m]     = (ull)v.x;
        wreg[2 * m + 1] = (ull)v.y;
    }

    // ---- X staging map: thread -> (row = tid>>3, 64B seg = tid&7) ----
    const int xr = tid >> 3, xs = tid & 7;
    uint32_t xsm[2];
    xsm[0] = (uint32_t)__cvta_generic_to_shared(&Xt[0][xr][xs * 16]);
    xsm[1] = (uint32_t)__cvta_generic_to_shared(&Xt[1][xr][xs * 16]);
    const size_t blockRow0 = (size_t)blockIdx.x * (TILES_PER_BLOCK * ROWS_PER_TILE);
    const float* xbase = X + (blockRow0 + xr) * INDIM + xs * 16;

    // tile 0 prologue
    #pragma unroll
    for (int i = 0; i < 4; ++i) cp_async16(xsm[0] + i * 16, xbase + i * 4);
    asm volatile("cp.async.commit_group;");
    asm volatile("cp.async.wait_group 0;");
    __syncthreads();

    ull acc[8];
    #pragma unroll
    for (int j = 0; j < 8; ++j) acc[j] = 0ull;

    for (int tile = 0; tile < TILES_PER_BLOCK; ++tile) {
        const int buf = tile & 1;
        if (tile + 1 < TILES_PER_BLOCK) {
            const float* p = xbase + (size_t)(tile + 1) * (ROWS_PER_TILE * INDIM);
            #pragma unroll
            for (int i = 0; i < 4; ++i) cp_async16(xsm[buf ^ 1] + i * 16, p + i * 4);
            asm volatile("cp.async.commit_group;");
        }

        #pragma unroll
        for (int q = 0; q < INDIM / 4; ++q) {        // fully unrolled: wreg idx static
            #pragma unroll
            for (int j = 0; j < 8; ++j) {
                longlong2 xv = *reinterpret_cast<const longlong2*>(
                    &Xt[buf][8 * rg + j][q * 4]);    // broadcast LDS.128
                ffma2(acc[j], (ull)xv.x, wreg[2 * q]);
                ffma2(acc[j], (ull)xv.y, wreg[2 * q + 1]);
            }
        }

        // epilogue: one float per (row, col); 128B-coalesced per warp
        size_t rb = blockRow0 + (size_t)tile * ROWS_PER_TILE + 8 * rg;
        #pragma unroll
        for (int j = 0; j < 8; ++j) {
            float2 a = unpackf2(acc[j]);
            Z[(rb + j) * NOUT + col] = a.x + a.y;
            acc[j] = 0ull;
        }

        asm volatile("cp.async.wait_group 0;");
        __syncthreads();
    }
}

// ---------------------------------------------------------------------------
// Phase 2: warp-per-row recurrence. lane = g*8+l owns units {2l,2l+1}.
// No reg cap (R7 spilled); ring index static via unroll 4.
// ---------------------------------------------------------------------------
__global__ __launch_bounds__(128, 2) void p2_rec(
    const float* __restrict__ Z,
    const float* __restrict__ Wf, const float* __restrict__ bf, const float* __restrict__ thf,
    const float* __restrict__ Wi, const float* __restrict__ bi, const float* __restrict__ thi,
    const float* __restrict__ Wg, const float* __restrict__ bg, const float* __restrict__ thg,
    const float* __restrict__ Wo, const float* __restrict__ bo, const float* __restrict__ tho,
    float* __restrict__ out)
{
    const int tid  = threadIdx.x;
    const int lane = tid & 31;
    const int warp = tid >> 5;
    const int g    = lane >> 3;
    const int l    = lane & 7;
    const int u0   = 2 * l, u1 = 2 * l + 1;
    const int row  = blockIdx.x * 4 + warp;
    const int hsrc = lane & 24;
    const unsigned FULL = 0xffffffffu;

    const float* Wsel = (g == 0) ? Wf : (g == 1) ? Wi : (g == 2) ? Wg : Wo;
    const float* bsel = (g == 0) ? bf : (g == 1) ? bi : (g == 2) ? bg : bo;
    const float* tsel = (g == 0) ? thf : (g == 1) ? thi : (g == 2) ? thg : tho;
    const float cth0 = bsel[u0] + tsel[u0];
    const float cth1 = bsel[u1] + tsel[u1];
    const float nqs  = (g == 2) ? -2.0f : -1.0f;
    const float sc2  = (g == 2) ?  2.0f :  1.0f;
    const float off2 = (g == 2) ? -1.0f :  0.0f;

    ull wh[HH];
    #pragma unroll
    for (int j = 0; j < HH; ++j)
        wh[j] = packf2(Wsel[u0 * DD + INDIM + j], Wsel[u1 * DD + INDIM + j]);

    const float* zp = Z + (size_t)row * NOUT + g * 16 + u0;
    const size_t zstep = (size_t)BB * NOUT;

    float2 zbuf[4];
    #pragma unroll
    for (int i = 0; i < 4; ++i)
        zbuf[i] = *reinterpret_cast<const float2*>(zp + (size_t)i * zstep);

    float h0 = 0.f, h1 = 0.f, c0 = 0.f, c1 = 0.f;
    float* outp = out + (size_t)row * HH + u0;

    #pragma unroll 4
    for (int t = 0; t < TT; ++t) {
        float2 zx = zbuf[t & 3];                      // static after unroll 4
        int tp = (t + 4 < TT) ? (t + 4) : (TT - 1);   // selp, no branch
        zbuf[t & 3] = *reinterpret_cast<const float2*>(zp + (size_t)tp * zstep);

        // ---- z += h . Wh : two independent ffma2 chains ----
        ull z1 = packf2(zx.x, zx.y), z2 = 0ull;
        ull hp = packf2(h0, h1);
        #pragma unroll
        for (int jj = 0; jj < 4; ++jj) {
            ull hj = __shfl_sync(FULL, hp, hsrc | jj);
            float2 hf = unpackf2(hj);
            ffma2(z1, packf2(hf.x, hf.x), wh[2 * jj]);
            ffma2(z1, packf2(hf.y, hf.y), wh[2 * jj + 1]);
        }
        #pragma unroll
        for (int jj = 4; jj < 8; ++jj) {
            ull hj = __shfl_sync(FULL, hp, hsrc | jj);
            float2 hf = unpackf2(hj);
            ffma2(z2, packf2(hf.x, hf.x), wh[2 * jj]);
            ffma2(z2, packf2(hf.y, hf.y), wh[2 * jj + 1]);
        }
        float2 zf = unpackf2(addf2(z1, z2));

        // ---- qgate: sin, then prefix scan + segment total concurrently ----
        float s0 = __sinf(zf.x + cth0);
        float s1 = __sinf(zf.y + cth1);
        float s01 = s0 + s1;
        float ps = s01, tt_ = s01;
        #pragma unroll
        for (int d = 1; d < 8; d <<= 1) {
            float v = __shfl_up_sync(FULL, ps, d, 8);
            ps += (l >= d) ? v : 0.0f;
            tt_ += __shfl_xor_sync(FULL, tt_, d, 8);
        }
        float cum1 = ps;
        float cum0 = ps - s1;
        float q0 = (l == 0) ? (s0 + tt_) : cum0;
        float q1 = cum1;

        // ---- branchless activation ----
        float e0 = __expf(q0 * nqs), e1 = __expf(q1 * nqs);
        float sg0 = __fdividef(1.0f, 1.0f + e0);
        float sg1 = __fdividef(1.0f, 1.0f + e1);
        float a0 = fmaf(sc2, sg0, off2);
        float a1 = fmaf(sc2, sg1, off2);

        // ---- gather gates for units (u0,u1) ----
        ull ap = packf2(a0, a1);
        ull fp_ = __shfl_sync(FULL, ap, l);
        ull ip_ = __shfl_sync(FULL, ap, 8 | l);
        ull gp_ = __shfl_sync(FULL, ap, 16 | l);
        ull op_ = __shfl_sync(FULL, ap, 24 | l);
        float2 fv = unpackf2(fp_), iv = unpackf2(ip_);
        float2 gv = unpackf2(gp_), ov = unpackf2(op_);

        c0 = fmaf(fv.x, c0, iv.x * gv.x);
        c1 = fmaf(fv.y, c1, iv.y * gv.y);
        h0 = ov.x * tanh_f(c0);
        h1 = ov.y * tanh_f(c1);

        // predicated store (no BSSY): only g==0 lanes write
        float* sp = outp + (size_t)t * (BB * HH);
        asm volatile(
            "{ .reg .pred p; setp.eq.s32 p, %0, 0;\n\t"
            "@p st.global.v2.f32 [%1], {%2, %3}; }"
            :: "r"(g), "l"(sp), "f"(h0), "f"(h1) : "memory");
    }

    if (g == 0) {
        size_t base = (size_t)TT * BB * HH;
        *reinterpret_cast<float2*>(out + base + (size_t)row * HH + u0) = make_float2(h0, h1);
        *reinterpret_cast<float2*>(out + base + (size_t)BB * HH + (size_t)row * HH + u0) = make_float2(c0, c1);
    }
}

extern "C" void kernel_launch(void* const* d_in, const int* in_sizes, int n_in,
                              void* d_out, int out_size) {
    (void)in_sizes; (void)n_in; (void)out_size;
    const float* X   = (const float*)d_in[0];
    const float* Wf  = (const float*)d_in[1];
    const float* bf  = (const float*)d_in[2];
    const float* thf = (const float*)d_in[3];
    const float* Wi  = (const float*)d_in[4];
    const float* bi  = (const float*)d_in[5];
    const float* thi = (const float*)d_in[6];
    const float* Wg  = (const float*)d_in[7];
    const float* bg  = (const float*)d_in[8];
    const float* thg = (const float*)d_in[9];
    const float* Wo  = (const float*)d_in[10];
    const float* bo  = (const float*)d_in[11];
    const float* tho = (const float*)d_in[12];
    float* out = (float*)d_out;

    float* Zp = nullptr;
    cudaGetSymbolAddress((void**)&Zp, g_Z);

    p1_gemm<<<P1_BLOCKS, 256>>>(X, Wf, Wi, Wg, Wo, Zp);
    p2_rec<<<BB / 4, 128>>>(Zp, Wf, bf, thf, Wi, bi, thi,
                            Wg, bg, thg, Wo, bo, tho, out);
}

// round 14
// speedup vs baseline: 1.5724x; 1.0359x over previous
#include <cuda_runtime.h>
#include <cstdint>

// QuantumLSTM v7.
// p1: Z = X @ Wx^T, weight-stationary with K SPLIT ACROSS WARPS:
//     block 512 thr = 16 warps = (kh, ch, rg); lane holds a K-half of one
//     output column (32 f32x2 regs) -> ~110 regs -> 4 warps/SMSP (R12's p1
//     had 2 and exposed LDS latency). kh-partials reduced via smem.
// p2: unchanged from R12 (362 us, warp-per-row, branch-free).

namespace {
constexpr int TT = 1024;
constexpr int BB = 1024;
constexpr int INDIM = 128;
constexpr int HH = 16;
constexpr int DD = 144;
constexpr int NOUT = 64;
constexpr size_t NROW = (size_t)TT * BB;
constexpr int RPT = 32;                    // rows per tile
constexpr int TPB = 32;                    // tiles per block
constexpr int P1_BLOCKS = (int)(NROW / (RPT * TPB)); // 1024
constexpr int KHALF = 64;                  // K elements per kh warp

typedef unsigned long long ull;

__device__ __forceinline__ void ffma2(ull &acc, ull a, ull b) {
    asm("fma.rn.f32x2 %0, %1, %2, %0;" : "+l"(acc) : "l"(a), "l"(b));
}
__device__ __forceinline__ ull addf2(ull a, ull b) {
    ull r; asm("add.rn.f32x2 %0, %1, %2;" : "=l"(r) : "l"(a), "l"(b)); return r;
}
__device__ __forceinline__ ull packf2(float lo, float hi) {
    ull r; asm("mov.b64 %0, {%1, %2};" : "=l"(r) : "f"(lo), "f"(hi)); return r;
}
__device__ __forceinline__ float2 unpackf2(ull v) {
    float lo, hi; asm("mov.b64 {%0, %1}, %2;" : "=f"(lo), "=f"(hi) : "l"(v));
    return make_float2(lo, hi);
}
__device__ __forceinline__ float tanh_f(float x) {
    float u = __expf(-2.0f * x);
    return __fdividef(1.0f - u, 1.0f + u);
}
__device__ __forceinline__ void cp_async16(uint32_t saddr, const float* g) {
    asm volatile("cp.async.ca.shared.global [%0], [%1], 16;" :: "r"(saddr), "l"(g));
}
}  // namespace

__device__ float g_Z[NROW * NOUT];   // 256 MB scratch

// ---------------------------------------------------------------------------
// Phase 1: Z[T*B,64] = X @ Wx^T. 512 thr, K split across warp pairs.
// ---------------------------------------------------------------------------
__global__ __launch_bounds__(512, 1) void p1_gemm(
    const float* __restrict__ X,
    const float* __restrict__ Wf, const float* __restrict__ Wi,
    const float* __restrict__ Wg, const float* __restrict__ Wo,
    float* __restrict__ Z)
{
    __shared__ __align__(16) float Xt[2][RPT][INDIM];      // 32 KB
    __shared__ __align__(16) float red[4][2][8][32];       // 8 KB: [rg][ch][j][lane]

    const int tid  = threadIdx.x;
    const int lane = tid & 31;
    const int warp = tid >> 5;      // 0..15
    const int rg   = warp & 3;      // rows 8*rg .. 8*rg+7
    const int ch   = (warp >> 2) & 1;  // cols ch*32 + lane
    const int kh   = warp >> 3;     // K half: [kh*64, kh*64+64)
    const int col  = ch * 32 + lane;

    // ---- W K-half for this column -> 32 packed f32x2 regs ----
    const float* Wsrc = (col < 16) ? Wf : (col < 32) ? Wi : (col < 48) ? Wg : Wo;
    const float* wrow = Wsrc + (col & 15) * DD + kh * KHALF;  // 16B aligned
    ull wreg[KHALF / 2];
    #pragma unroll
    for (int m = 0; m < KHALF / 4; ++m) {      // 16 x float4
        longlong2 v = reinterpret_cast<const longlong2*>(wrow)[m];
        wreg[2 * m]     = (ull)v.x;
        wreg[2 * m + 1] = (ull)v.y;
    }

    // ---- X staging: 1024 16B chunks/tile, 2 per thread ----
    // chunk c: row = c>>5, seg = c&31
    const size_t blockRow0 = (size_t)blockIdx.x * (TPB * RPT);
    const int c0 = tid, c1 = tid + 512;
    uint32_t xs0[2], xs1[2];
    xs0[0] = (uint32_t)__cvta_generic_to_shared(&Xt[0][c0 >> 5][(c0 & 31) * 4]);
    xs0[1] = (uint32_t)__cvta_generic_to_shared(&Xt[1][c0 >> 5][(c0 & 31) * 4]);
    xs1[0] = (uint32_t)__cvta_generic_to_shared(&Xt[0][c1 >> 5][(c1 & 31) * 4]);
    xs1[1] = (uint32_t)__cvta_generic_to_shared(&Xt[1][c1 >> 5][(c1 & 31) * 4]);
    const float* xg0 = X + (blockRow0 + (c0 >> 5)) * INDIM + (c0 & 31) * 4;
    const float* xg1 = X + (blockRow0 + (c1 >> 5)) * INDIM + (c1 & 31) * 4;

    cp_async16(xs0[0], xg0);
    cp_async16(xs1[0], xg1);
    asm volatile("cp.async.commit_group;");
    asm volatile("cp.async.wait_group 0;");
    __syncthreads();

    ull acc[8];
    #pragma unroll
    for (int j = 0; j < 8; ++j) acc[j] = 0ull;

    for (int tile = 0; tile < TPB; ++tile) {
        const int buf = tile & 1;
        if (tile + 1 < TPB) {
            size_t off = (size_t)(tile + 1) * (RPT * INDIM);
            cp_async16(xs0[buf ^ 1], xg0 + off);
            cp_async16(xs1[buf ^ 1], xg1 + off);
            asm volatile("cp.async.commit_group;");
        }

        #pragma unroll
        for (int q = 0; q < KHALF / 4; ++q) {      // 16 quads in this K-half
            #pragma unroll
            for (int j = 0; j < 8; ++j) {
                longlong2 xv = *reinterpret_cast<const longlong2*>(
                    &Xt[buf][8 * rg + j][kh * KHALF + q * 4]);  // broadcast LDS.128
                ffma2(acc[j], (ull)xv.x, wreg[2 * q]);
                ffma2(acc[j], (ull)xv.y, wreg[2 * q + 1]);
            }
        }

        // ---- kh reduction + store ----
        float s[8];
        #pragma unroll
        for (int j = 0; j < 8; ++j) {
            float2 a = unpackf2(acc[j]);
            s[j] = a.x + a.y;
            acc[j] = 0ull;
        }
        if (kh == 1) {
            #pragma unroll
            for (int j = 0; j < 8; ++j) red[rg][ch][j][lane] = s[j];
        }
        __syncthreads();
        if (kh == 0) {
            size_t rb = blockRow0 + (size_t)tile * RPT + 8 * rg;
            #pragma unroll
            for (int j = 0; j < 8; ++j)
                Z[(rb + j) * NOUT + col] = s[j] + red[rg][ch][j][lane];
        }

        asm volatile("cp.async.wait_group 0;");
        __syncthreads();     // red + Xt[buf] safe to reuse
    }
}

// ---------------------------------------------------------------------------
// Phase 2: unchanged from R12 (362 us). Warp-per-row recurrence.
// ---------------------------------------------------------------------------
__global__ __launch_bounds__(128, 2) void p2_rec(
    const float* __restrict__ Z,
    const float* __restrict__ Wf, const float* __restrict__ bf, const float* __restrict__ thf,
    const float* __restrict__ Wi, const float* __restrict__ bi, const float* __restrict__ thi,
    const float* __restrict__ Wg, const float* __restrict__ bg, const float* __restrict__ thg,
    const float* __restrict__ Wo, const float* __restrict__ bo, const float* __restrict__ tho,
    float* __restrict__ out)
{
    const int tid  = threadIdx.x;
    const int lane = tid & 31;
    const int warp = tid >> 5;
    const int g    = lane >> 3;
    const int l    = lane & 7;
    const int u0   = 2 * l, u1 = 2 * l + 1;
    const int row  = blockIdx.x * 4 + warp;
    const int hsrc = lane & 24;
    const unsigned FULL = 0xffffffffu;

    const float* Wsel = (g == 0) ? Wf : (g == 1) ? Wi : (g == 2) ? Wg : Wo;
    const float* bsel = (g == 0) ? bf : (g == 1) ? bi : (g == 2) ? bg : bo;
    const float* tsel = (g == 0) ? thf : (g == 1) ? thi : (g == 2) ? thg : tho;
    const float cth0 = bsel[u0] + tsel[u0];
    const float cth1 = bsel[u1] + tsel[u1];
    const float nqs  = (g == 2) ? -2.0f : -1.0f;
    const float sc2  = (g == 2) ?  2.0f :  1.0f;
    const float off2 = (g == 2) ? -1.0f :  0.0f;

    ull wh[HH];
    #pragma unroll
    for (int j = 0; j < HH; ++j)
        wh[j] = packf2(Wsel[u0 * DD + INDIM + j], Wsel[u1 * DD + INDIM + j]);

    const float* zp = Z + (size_t)row * NOUT + g * 16 + u0;
    const size_t zstep = (size_t)BB * NOUT;

    float2 zbuf[4];
    #pragma unroll
    for (int i = 0; i < 4; ++i)
        zbuf[i] = *reinterpret_cast<const float2*>(zp + (size_t)i * zstep);

    float h0 = 0.f, h1 = 0.f, c0 = 0.f, c1 = 0.f;
    float* outp = out + (size_t)row * HH + u0;

    #pragma unroll 4
    for (int t = 0; t < TT; ++t) {
        float2 zx = zbuf[t & 3];
        int tp = (t + 4 < TT) ? (t + 4) : (TT - 1);
        zbuf[t & 3] = *reinterpret_cast<const float2*>(zp + (size_t)tp * zstep);

        ull z1 = packf2(zx.x, zx.y), z2 = 0ull;
        ull hp = packf2(h0, h1);
        #pragma unroll
        for (int jj = 0; jj < 4; ++jj) {
            ull hj = __shfl_sync(FULL, hp, hsrc | jj);
            float2 hf = unpackf2(hj);
            ffma2(z1, packf2(hf.x, hf.x), wh[2 * jj]);
            ffma2(z1, packf2(hf.y, hf.y), wh[2 * jj + 1]);
        }
        #pragma unroll
        for (int jj = 4; jj < 8; ++jj) {
            ull hj = __shfl_sync(FULL, hp, hsrc | jj);
            float2 hf = unpackf2(hj);
            ffma2(z2, packf2(hf.x, hf.x), wh[2 * jj]);
            ffma2(z2, packf2(hf.y, hf.y), wh[2 * jj + 1]);
        }
        float2 zf = unpackf2(addf2(z1, z2));

        float s0 = __sinf(zf.x + cth0);
        float s1 = __sinf(zf.y + cth1);
        float s01 = s0 + s1;
        float ps = s01, tt_ = s01;
        #pragma unroll
        for (int d = 1; d < 8; d <<= 1) {
            float v = __shfl_up_sync(FULL, ps, d, 8);
            ps += (l >= d) ? v : 0.0f;
            tt_ += __shfl_xor_sync(FULL, tt_, d, 8);
        }
        float cum1 = ps;
        float cum0 = ps - s1;
        float q0 = (l == 0) ? (s0 + tt_) : cum0;
        float q1 = cum1;

        float e0 = __expf(q0 * nqs), e1 = __expf(q1 * nqs);
        float sg0 = __fdividef(1.0f, 1.0f + e0);
        float sg1 = __fdividef(1.0f, 1.0f + e1);
        float a0 = fmaf(sc2, sg0, off2);
        float a1 = fmaf(sc2, sg1, off2);

        ull ap = packf2(a0, a1);
        ull fp_ = __shfl_sync(FULL, ap, l);
        ull ip_ = __shfl_sync(FULL, ap, 8 | l);
        ull gp_ = __shfl_sync(FULL, ap, 16 | l);
        ull op_ = __shfl_sync(FULL, ap, 24 | l);
        float2 fv = unpackf2(fp_), iv = unpackf2(ip_);
        float2 gv = unpackf2(gp_), ov = unpackf2(op_);

        c0 = fmaf(fv.x, c0, iv.x * gv.x);
        c1 = fmaf(fv.y, c1, iv.y * gv.y);
        h0 = ov.x * tanh_f(c0);
        h1 = ov.y * tanh_f(c1);

        float* sp = outp + (size_t)t * (BB * HH);
        asm volatile(
            "{ .reg .pred p; setp.eq.s32 p, %0, 0;\n\t"
            "@p st.global.v2.f32 [%1], {%2, %3}; }"
            :: "r"(g), "l"(sp), "f"(h0), "f"(h1) : "memory");
    }

    if (g == 0) {
        size_t base = (size_t)TT * BB * HH;
        *reinterpret_cast<float2*>(out + base + (size_t)row * HH + u0) = make_float2(h0, h1);
        *reinterpret_cast<float2*>(out + base + (size_t)BB * HH + (size_t)row * HH + u0) = make_float2(c0, c1);
    }
}

extern "C" void kernel_launch(void* const* d_in, const int* in_sizes, int n_in,
                              void* d_out, int out_size) {
    (void)in_sizes; (void)n_in; (void)out_size;
    const float* X   = (const float*)d_in[0];
    const float* Wf  = (const float*)d_in[1];
    const float* bf  = (const float*)d_in[2];
    const float* thf = (const float*)d_in[3];
    const float* Wi  = (const float*)d_in[4];
    const float* bi  = (const float*)d_in[5];
    const float* thi = (const float*)d_in[6];
    const float* Wg  = (const float*)d_in[7];
    const float* bg  = (const float*)d_in[8];
    const float* thg = (const float*)d_in[9];
    const float* Wo  = (const float*)d_in[10];
    const float* bo  = (const float*)d_in[11];
    const float* tho = (const float*)d_in[12];
    float* out = (float*)d_out;

    float* Zp = nullptr;
    cudaGetSymbolAddress((void**)&Zp, g_Z);

    p1_gemm<<<P1_BLOCKS, 512>>>(X, Wf, Wi, Wg, Wo, Zp);
    p2_rec<<<BB / 4, 128>>>(Zp, Wf, bf, thf, Wi, bi, thi,
                            Wg, bg, thg, Wo, bo, tho, out);
}

// round 15
// speedup vs baseline: 2.5929x; 1.6490x over previous
#include <cuda_runtime.h>
#include <cuda_bf16.h>
#include <cstdint>

// QuantumLSTM v8: tensor-core p1.
// p1: Z[T*B,64] = X @ Wx^T via mma.sync.m16n8k16 bf16 with hi/lo split:
//     Z = Xh@Wh + Xh@Wl + Xl@Wh  (lo*lo term ~2^-18, dropped).
//     W fragments prepacked by p0 into a 32KB lane-indexed table -> smem.
//     A fragments: direct fp32 LDG + in-register bf16x2 split. X read once.
// p2: unchanged from R12/R14 (360 us, warp-per-row recurrence).

namespace {
constexpr int TT = 1024;
constexpr int BB = 1024;
constexpr int INDIM = 128;
constexpr int HH = 16;
constexpr int DD = 144;
constexpr int NOUT = 64;
constexpr size_t NROW = (size_t)TT * BB;
constexpr int NFRAG = 8 * 8 * 2 * 32;          // ks * nt * var * lane = 4096
constexpr int MT_PER_WARP = 8;
constexpr int P1_BLOCKS = (int)(NROW / 16 / 4 / MT_PER_WARP);  // 2048

typedef unsigned long long ull;

__device__ __forceinline__ ull packf2(float lo, float hi) {
    ull r; asm("mov.b64 %0, {%1, %2};" : "=l"(r) : "f"(lo), "f"(hi)); return r;
}
__device__ __forceinline__ float2 unpackf2(ull v) {
    float lo, hi; asm("mov.b64 {%0, %1}, %2;" : "=f"(lo), "=f"(hi) : "l"(v));
    return make_float2(lo, hi);
}
__device__ __forceinline__ void ffma2(ull &acc, ull a, ull b) {
    asm("fma.rn.f32x2 %0, %1, %2, %0;" : "+l"(acc) : "l"(a), "l"(b));
}
__device__ __forceinline__ ull addf2(ull a, ull b) {
    ull r; asm("add.rn.f32x2 %0, %1, %2;" : "=l"(r) : "l"(a), "l"(b)); return r;
}
__device__ __forceinline__ float tanh_f(float x) {
    float u = __expf(-2.0f * x);
    return __fdividef(1.0f - u, 1.0f + u);
}
__device__ __forceinline__ void mma16816(float* c, const uint32_t* a, uint2 b) {
    asm volatile(
        "mma.sync.aligned.m16n8k16.row.col.f32.bf16.bf16.f32 "
        "{%0,%1,%2,%3}, {%4,%5,%6,%7}, {%8,%9}, {%0,%1,%2,%3};"
        : "+f"(c[0]), "+f"(c[1]), "+f"(c[2]), "+f"(c[3])
        : "r"(a[0]), "r"(a[1]), "r"(a[2]), "r"(a[3]), "r"(b.x), "r"(b.y));
}
// fp32 pair -> (bf16x2 hi, bf16x2 lo). Element order: .x in low 16 bits,
// matching mma's k-even-in-low-bits convention.
__device__ __forceinline__ void split2(float2 v, uint32_t& hi, uint32_t& lo) {
    __nv_bfloat162 h = __float22bfloat162_rn(v);
    float hx = __bfloat162float(h.x), hy = __bfloat162float(h.y);
    __nv_bfloat162 l = __float22bfloat162_rn(make_float2(v.x - hx, v.y - hy));
    hi = *reinterpret_cast<uint32_t*>(&h);
    lo = *reinterpret_cast<uint32_t*>(&l);
}
}  // namespace

__device__ float g_Z[NROW * NOUT];      // 256 MB scratch
__device__ uint2 g_Bfrag[NFRAG];        // 32 KB prepacked W fragments

// ---------------------------------------------------------------------------
// p0: prepack B fragments. Fragment layout for m16n8k16 (row.col), lane
// (gid = lane>>2, tig = lane&3): b0 = {W[k0][n], W[k0+1][n]}, b1 = {W[k0+8][n],
// W[k0+9][n]} with k0 = 16*ks + 2*tig, n = nt*8 + gid. var 0 = bf16(hi),
// var 1 = bf16(w - hi).
// ---------------------------------------------------------------------------
__global__ void p0_prep(const float* __restrict__ Wf, const float* __restrict__ Wi,
                        const float* __restrict__ Wg, const float* __restrict__ Wo)
{
    int e = blockIdx.x * blockDim.x + threadIdx.x;
    if (e >= NFRAG) return;
    int lane = e & 31;
    int var  = (e >> 5) & 1;
    int nt   = (e >> 6) & 7;
    int ks   = (e >> 9) & 7;
    int gid = lane >> 2, tig = lane & 3;
    int n = nt * 8 + gid;
    const float* Wsrc = (n < 16) ? Wf : (n < 32) ? Wi : (n < 48) ? Wg : Wo;

    auto wv = [&](int k) -> __nv_bfloat16 {
        float w = Wsrc[(n & 15) * DD + k];
        __nv_bfloat16 hi = __float2bfloat16(w);
        if (var == 0) return hi;
        return __float2bfloat16(w - __bfloat162float(hi));
    };
    int k0 = ks * 16 + 2 * tig;
    __nv_bfloat162 b0, b1;
    b0.x = wv(k0);     b0.y = wv(k0 + 1);
    b1.x = wv(k0 + 8); b1.y = wv(k0 + 9);
    uint2 v;
    v.x = *reinterpret_cast<uint32_t*>(&b0);
    v.y = *reinterpret_cast<uint32_t*>(&b1);
    g_Bfrag[e] = v;
}

// ---------------------------------------------------------------------------
// p1: Z = X @ Wx^T, tensor cores. Block 128 thr = 4 warps; warp does 8
// consecutive 16-row m-tiles; 8 n-tiles (N=64); K=128 in 8 ksteps; 3 split
// combos accumulated in fp32.
// ---------------------------------------------------------------------------
__global__ __launch_bounds__(128, 4) void p1_mma(
    const float* __restrict__ X, float* __restrict__ Z)
{
    __shared__ uint2 sB[NFRAG];   // 32 KB

    const int tid = threadIdx.x;
    {   // copy fragment table: 2048 uint4, 16 per thread
        const uint4* src = reinterpret_cast<const uint4*>(g_Bfrag);
        uint4* dst = reinterpret_cast<uint4*>(sB);
        #pragma unroll
        for (int i = 0; i < 16; ++i) dst[tid + 128 * i] = src[tid + 128 * i];
    }
    __syncthreads();

    const int lane = tid & 31;
    const int warp = tid >> 5;
    const int gid = lane >> 2, tig = lane & 3;
    const int warpGlobal = blockIdx.x * 4 + warp;

    for (int i = 0; i < MT_PER_WARP; ++i) {
        const size_t rowBase = ((size_t)warpGlobal * MT_PER_WARP + i) * 16;
        const float* xr = X + (rowBase + gid) * INDIM + 2 * tig;

        float acc[8][4];
        #pragma unroll
        for (int nt = 0; nt < 8; ++nt)
            acc[nt][0] = acc[nt][1] = acc[nt][2] = acc[nt][3] = 0.0f;

        #pragma unroll
        for (int ks = 0; ks < 8; ++ks) {
            float2 xa = *reinterpret_cast<const float2*>(xr + ks * 16);              // (gid,   klo)
            float2 xb = *reinterpret_cast<const float2*>(xr + 8 * INDIM + ks * 16);  // (gid+8, klo)
            float2 xc = *reinterpret_cast<const float2*>(xr + ks * 16 + 8);          // (gid,   khi)
            float2 xd = *reinterpret_cast<const float2*>(xr + 8 * INDIM + ks * 16 + 8);
            uint32_t ah[4], al[4];
            split2(xa, ah[0], al[0]);
            split2(xb, ah[1], al[1]);
            split2(xc, ah[2], al[2]);
            split2(xd, ah[3], al[3]);

            #pragma unroll
            for (int nt = 0; nt < 8; ++nt) {
                uint2 bh = sB[((ks * 8 + nt) * 2 + 0) * 32 + lane];
                uint2 bl = sB[((ks * 8 + nt) * 2 + 1) * 32 + lane];
                mma16816(acc[nt], ah, bh);   // Xh @ Wh
                mma16816(acc[nt], ah, bl);   // Xh @ Wl
                mma16816(acc[nt], al, bh);   // Xl @ Wh
            }
        }

        // C layout: c0,c1 = (row gid, cols 2tig,2tig+1); c2,c3 = row gid+8.
        float* z0 = Z + (rowBase + gid) * NOUT + 2 * tig;
        float* z1 = Z + (rowBase + gid + 8) * NOUT + 2 * tig;
        #pragma unroll
        for (int nt = 0; nt < 8; ++nt) {
            *reinterpret_cast<float2*>(z0 + nt * 8) = make_float2(acc[nt][0], acc[nt][1]);
            *reinterpret_cast<float2*>(z1 + nt * 8) = make_float2(acc[nt][2], acc[nt][3]);
        }
    }
}

// ---------------------------------------------------------------------------
// p2: unchanged (R12). Warp-per-row recurrence, branch-free body.
// ---------------------------------------------------------------------------
__global__ __launch_bounds__(128, 2) void p2_rec(
    const float* __restrict__ Z,
    const float* __restrict__ Wf, const float* __restrict__ bf, const float* __restrict__ thf,
    const float* __restrict__ Wi, const float* __restrict__ bi, const float* __restrict__ thi,
    const float* __restrict__ Wg, const float* __restrict__ bg, const float* __restrict__ thg,
    const float* __restrict__ Wo, const float* __restrict__ bo, const float* __restrict__ tho,
    float* __restrict__ out)
{
    const int tid  = threadIdx.x;
    const int lane = tid & 31;
    const int warp = tid >> 5;
    const int g    = lane >> 3;
    const int l    = lane & 7;
    const int u0   = 2 * l, u1 = 2 * l + 1;
    const int row  = blockIdx.x * 4 + warp;
    const int hsrc = lane & 24;
    const unsigned FULL = 0xffffffffu;

    const float* Wsel = (g == 0) ? Wf : (g == 1) ? Wi : (g == 2) ? Wg : Wo;
    const float* bsel = (g == 0) ? bf : (g == 1) ? bi : (g == 2) ? bg : bo;
    const float* tsel = (g == 0) ? thf : (g == 1) ? thi : (g == 2) ? thg : tho;
    const float cth0 = bsel[u0] + tsel[u0];
    const float cth1 = bsel[u1] + tsel[u1];
    const float nqs  = (g == 2) ? -2.0f : -1.0f;
    const float sc2  = (g == 2) ?  2.0f :  1.0f;
    const float off2 = (g == 2) ? -1.0f :  0.0f;

    ull wh[HH];
    #pragma unroll
    for (int j = 0; j < HH; ++j)
        wh[j] = packf2(Wsel[u0 * DD + INDIM + j], Wsel[u1 * DD + INDIM + j]);

    const float* zp = Z + (size_t)row * NOUT + g * 16 + u0;
    const size_t zstep = (size_t)BB * NOUT;

    float2 zbuf[4];
    #pragma unroll
    for (int i = 0; i < 4; ++i)
        zbuf[i] = *reinterpret_cast<const float2*>(zp + (size_t)i * zstep);

    float h0 = 0.f, h1 = 0.f, c0 = 0.f, c1 = 0.f;
    float* outp = out + (size_t)row * HH + u0;

    #pragma unroll 4
    for (int t = 0; t < TT; ++t) {
        float2 zx = zbuf[t & 3];
        int tp = (t + 4 < TT) ? (t + 4) : (TT - 1);
        zbuf[t & 3] = *reinterpret_cast<const float2*>(zp + (size_t)tp * zstep);

        ull z1 = packf2(zx.x, zx.y), z2 = 0ull;
        ull hp = packf2(h0, h1);
        #pragma unroll
        for (int jj = 0; jj < 4; ++jj) {
            ull hj = __shfl_sync(FULL, hp, hsrc | jj);
            float2 hf = unpackf2(hj);
            ffma2(z1, packf2(hf.x, hf.x), wh[2 * jj]);
            ffma2(z1, packf2(hf.y, hf.y), wh[2 * jj + 1]);
        }
        #pragma unroll
        for (int jj = 4; jj < 8; ++jj) {
            ull hj = __shfl_sync(FULL, hp, hsrc | jj);
            float2 hf = unpackf2(hj);
            ffma2(z2, packf2(hf.x, hf.x), wh[2 * jj]);
            ffma2(z2, packf2(hf.y, hf.y), wh[2 * jj + 1]);
        }
        float2 zf = unpackf2(addf2(z1, z2));

        float s0 = __sinf(zf.x + cth0);
        float s1 = __sinf(zf.y + cth1);
        float s01 = s0 + s1;
        float ps = s01, tt_ = s01;
        #pragma unroll
        for (int d = 1; d < 8; d <<= 1) {
            float v = __shfl_up_sync(FULL, ps, d, 8);
            ps += (l >= d) ? v : 0.0f;
            tt_ += __shfl_xor_sync(FULL, tt_, d, 8);
        }
        float cum1 = ps;
        float cum0 = ps - s1;
        float q0 = (l == 0) ? (s0 + tt_) : cum0;
        float q1 = cum1;

        float e0 = __expf(q0 * nqs), e1 = __expf(q1 * nqs);
        float sg0 = __fdividef(1.0f, 1.0f + e0);
        float sg1 = __fdividef(1.0f, 1.0f + e1);
        float a0 = fmaf(sc2, sg0, off2);
        float a1 = fmaf(sc2, sg1, off2);

        ull ap = packf2(a0, a1);
        ull fp_ = __shfl_sync(FULL, ap, l);
        ull ip_ = __shfl_sync(FULL, ap, 8 | l);
        ull gp_ = __shfl_sync(FULL, ap, 16 | l);
        ull op_ = __shfl_sync(FULL, ap, 24 | l);
        float2 fv = unpackf2(fp_), iv = unpackf2(ip_);
        float2 gv = unpackf2(gp_), ov = unpackf2(op_);

        c0 = fmaf(fv.x, c0, iv.x * gv.x);
        c1 = fmaf(fv.y, c1, iv.y * gv.y);
        h0 = ov.x * tanh_f(c0);
        h1 = ov.y * tanh_f(c1);

        float* sp = outp + (size_t)t * (BB * HH);
        asm volatile(
            "{ .reg .pred p; setp.eq.s32 p, %0, 0;\n\t"
            "@p st.global.v2.f32 [%1], {%2, %3}; }"
            :: "r"(g), "l"(sp), "f"(h0), "f"(h1) : "memory");
    }

    if (g == 0) {
        size_t base = (size_t)TT * BB * HH;
        *reinterpret_cast<float2*>(out + base + (size_t)row * HH + u0) = make_float2(h0, h1);
        *reinterpret_cast<float2*>(out + base + (size_t)BB * HH + (size_t)row * HH + u0) = make_float2(c0, c1);
    }
}

extern "C" void kernel_launch(void* const* d_in, const int* in_sizes, int n_in,
                              void* d_out, int out_size) {
    (void)in_sizes; (void)n_in; (void)out_size;
    const float* X   = (const float*)d_in[0];
    const float* Wf  = (const float*)d_in[1];
    const float* bf  = (const float*)d_in[2];
    const float* thf = (const float*)d_in[3];
    const float* Wi  = (const float*)d_in[4];
    const float* bi  = (const float*)d_in[5];
    const float* thi = (const float*)d_in[6];
    const float* Wg  = (const float*)d_in[7];
    const float* bg  = (const float*)d_in[8];
    const float* thg = (const float*)d_in[9];
    const float* Wo  = (const float*)d_in[10];
    const float* bo  = (const float*)d_in[11];
    const float* tho = (const float*)d_in[12];
    float* out = (float*)d_out;

    float* Zp = nullptr;
    cudaGetSymbolAddress((void**)&Zp, g_Z);

    p0_prep<<<NFRAG / 128, 128>>>(Wf, Wi, Wg, Wo);
    p1_mma<<<P1_BLOCKS, 128>>>(X, Zp);
    p2_rec<<<BB / 4, 128>>>(Zp, Wf, bf, thf, Wi, bi, thi,
                            Wg, bg, thg, Wo, bo, tho, out);
}

// round 17
// speedup vs baseline: 2.6334x; 1.0156x over previous
#include <cuda_runtime.h>
#include <cuda_bf16.h>
#include <cstdint>

// QuantumLSTM v9.
// p1: tensor-core (mma.sync bf16 hi/lo 3-pass) — unchanged from R15 (188 us).
// p2: recurrence chain compressed: transposed-paired Wh (no splat packs),
//     radix-4 segmented scan (3-round -> 2-round chain), padded-Z unclamped
//     ring-4 prefetch, pointer-walk addressing.

namespace {
constexpr int TT = 1024;
constexpr int BB = 1024;
constexpr int INDIM = 128;
constexpr int HH = 16;
constexpr int DD = 144;
constexpr int NOUT = 64;
constexpr size_t NROW = (size_t)TT * BB;
constexpr int NFRAG = 8 * 8 * 2 * 32;
constexpr int MT_PER_WARP = 8;
constexpr int P1_BLOCKS = (int)(NROW / 16 / 4 / MT_PER_WARP);  // 2048

typedef unsigned long long ull;

__device__ __forceinline__ ull packf2(float lo, float hi) {
    ull r; asm("mov.b64 %0, {%1, %2};" : "=l"(r) : "f"(lo), "f"(hi)); return r;
}
__device__ __forceinline__ float2 unpackf2(ull v) {
    float lo, hi; asm("mov.b64 {%0, %1}, %2;" : "=f"(lo), "=f"(hi) : "l"(v));
    return make_float2(lo, hi);
}
__device__ __forceinline__ void ffma2(ull &acc, ull a, ull b) {
    asm("fma.rn.f32x2 %0, %1, %2, %0;" : "+l"(acc) : "l"(a), "l"(b));
}
__device__ __forceinline__ ull addf2(ull a, ull b) {
    ull r; asm("add.rn.f32x2 %0, %1, %2;" : "=l"(r) : "l"(a), "l"(b)); return r;
}
__device__ __forceinline__ void mma16816(float* c, const uint32_t* a, uint2 b) {
    asm volatile(
        "mma.sync.aligned.m16n8k16.row.col.f32.bf16.bf16.f32 "
        "{%0,%1,%2,%3}, {%4,%5,%6,%7}, {%8,%9}, {%0,%1,%2,%3};"
        : "+f"(c[0]), "+f"(c[1]), "+f"(c[2]), "+f"(c[3])
        : "r"(a[0]), "r"(a[1]), "r"(a[2]), "r"(a[3]), "r"(b.x), "r"(b.y));
}
__device__ __forceinline__ void split2(float2 v, uint32_t& hi, uint32_t& lo) {
    __nv_bfloat162 h = __float22bfloat162_rn(v);
    float hx = __bfloat162float(h.x), hy = __bfloat162float(h.y);
    __nv_bfloat162 l = __float22bfloat162_rn(make_float2(v.x - hx, v.y - hy));
    hi = *reinterpret_cast<uint32_t*>(&h);
    lo = *reinterpret_cast<uint32_t*>(&l);
}
}  // namespace

// Z scratch padded by 4 time-slices so the ring-4 prefetch needs no clamp.
__device__ float g_Z[(NROW + 4 * BB) * NOUT];
__device__ uint2 g_Bfrag[NFRAG];        // 32 KB prepacked W fragments

// ---------------------------------------------------------------------------
// p0: prepack B fragments (unchanged).
// ---------------------------------------------------------------------------
__global__ void p0_prep(const float* __restrict__ Wf, const float* __restrict__ Wi,
                        const float* __restrict__ Wg, const float* __restrict__ Wo)
{
    int e = blockIdx.x * blockDim.x + threadIdx.x;
    if (e >= NFRAG) return;
    int lane = e & 31;
    int var  = (e >> 5) & 1;
    int nt   = (e >> 6) & 7;
    int ks   = (e >> 9) & 7;
    int gid = lane >> 2, tig = lane & 3;
    int n = nt * 8 + gid;
    const float* Wsrc = (n < 16) ? Wf : (n < 32) ? Wi : (n < 48) ? Wg : Wo;

    auto wv = [&](int k) -> __nv_bfloat16 {
        float w = Wsrc[(n & 15) * DD + k];
        __nv_bfloat16 hi = __float2bfloat16(w);
        if (var == 0) return hi;
        return __float2bfloat16(w - __bfloat162float(hi));
    };
    int k0 = ks * 16 + 2 * tig;
    __nv_bfloat162 b0, b1;
    b0.x = wv(k0);     b0.y = wv(k0 + 1);
    b1.x = wv(k0 + 8); b1.y = wv(k0 + 9);
    uint2 v;
    v.x = *reinterpret_cast<uint32_t*>(&b0);
    v.y = *reinterpret_cast<uint32_t*>(&b1);
    g_Bfrag[e] = v;
}

// ---------------------------------------------------------------------------
// p1: Z = X @ Wx^T, tensor cores (unchanged from R15).
// ---------------------------------------------------------------------------
__global__ __launch_bounds__(128, 4) void p1_mma(
    const float* __restrict__ X, float* __restrict__ Z)
{
    __shared__ uint2 sB[NFRAG];   // 32 KB

    const int tid = threadIdx.x;
    {
        const uint4* src = reinterpret_cast<const uint4*>(g_Bfrag);
        uint4* dst = reinterpret_cast<uint4*>(sB);
        #pragma unroll
        for (int i = 0; i < 16; ++i) dst[tid + 128 * i] = src[tid + 128 * i];
    }
    __syncthreads();

    const int lane = tid & 31;
    const int warp = tid >> 5;
    const int gid = lane >> 2, tig = lane & 3;
    const int warpGlobal = blockIdx.x * 4 + warp;

    for (int i = 0; i < MT_PER_WARP; ++i) {
        const size_t rowBase = ((size_t)warpGlobal * MT_PER_WARP + i) * 16;
        const float* xr = X + (rowBase + gid) * INDIM + 2 * tig;

        float acc[8][4];
        #pragma unroll
        for (int nt = 0; nt < 8; ++nt)
            acc[nt][0] = acc[nt][1] = acc[nt][2] = acc[nt][3] = 0.0f;

        #pragma unroll
        for (int ks = 0; ks < 8; ++ks) {
            float2 xa = *reinterpret_cast<const float2*>(xr + ks * 16);
            float2 xb = *reinterpret_cast<const float2*>(xr + 8 * INDIM + ks * 16);
            float2 xc = *reinterpret_cast<const float2*>(xr + ks * 16 + 8);
            float2 xd = *reinterpret_cast<const float2*>(xr + 8 * INDIM + ks * 16 + 8);
            uint32_t ah[4], al[4];
            split2(xa, ah[0], al[0]);
            split2(xb, ah[1], al[1]);
            split2(xc, ah[2], al[2]);
            split2(xd, ah[3], al[3]);

            #pragma unroll
            for (int nt = 0; nt < 8; ++nt) {
                uint2 bh = sB[((ks * 8 + nt) * 2 + 0) * 32 + lane];
                uint2 bl = sB[((ks * 8 + nt) * 2 + 1) * 32 + lane];
                mma16816(acc[nt], ah, bh);
                mma16816(acc[nt], ah, bl);
                mma16816(acc[nt], al, bh);
            }
        }

        float* z0 = Z + (rowBase + gid) * NOUT + 2 * tig;
        float* z1 = Z + (rowBase + gid + 8) * NOUT + 2 * tig;
        #pragma unroll
        for (int nt = 0; nt < 8; ++nt) {
            *reinterpret_cast<float2*>(z0 + nt * 8) = make_float2(acc[nt][0], acc[nt][1]);
            *reinterpret_cast<float2*>(z1 + nt * 8) = make_float2(acc[nt][2], acc[nt][3]);
        }
    }
}

// ---------------------------------------------------------------------------
// p2: warp-per-row recurrence, chain-compressed.
// lane = g*8 + l owns units {2l, 2l+1} of gate g.
// ---------------------------------------------------------------------------
__global__ __launch_bounds__(128, 2) void p2_rec(
    const float* __restrict__ Z,
    const float* __restrict__ Wf, const float* __restrict__ bf, const float* __restrict__ thf,
    const float* __restrict__ Wi, const float* __restrict__ bi, const float* __restrict__ thi,
    const float* __restrict__ Wg, const float* __restrict__ bg, const float* __restrict__ thg,
    const float* __restrict__ Wo, const float* __restrict__ bo, const float* __restrict__ tho,
    float* __restrict__ out)
{
    const int tid  = threadIdx.x;
    const int lane = tid & 31;
    const int warp = tid >> 5;
    const int g    = lane >> 3;
    const int l    = lane & 7;
    const int u0   = 2 * l, u1 = 2 * l + 1;
    const int row  = blockIdx.x * 4 + warp;
    const int hsrc = lane & 24;
    const unsigned FULL = 0xffffffffu;

    const float* Wsel = (g == 0) ? Wf : (g == 1) ? Wi : (g == 2) ? Wg : Wo;
    const float* bsel = (g == 0) ? bf : (g == 1) ? bi : (g == 2) ? bg : bo;
    const float* tsel = (g == 0) ? thf : (g == 1) ? thi : (g == 2) ? thg : tho;
    const float cth0 = bsel[u0] + tsel[u0];
    const float cth1 = bsel[u1] + tsel[u1];
    const float nqs  = (g == 2) ? -2.0f : -1.0f;
    const float sc2  = (g == 2) ?  2.0f :  1.0f;
    const float off2 = (g == 2) ? -1.0f :  0.0f;

    // Transposed-paired recurrent weights: whA[j] multiplies the packed h-pair
    // {h_2j, h_2j+1} directly (no splat needed):
    //   whA[j] = {W[u0][128+2j], W[u0][128+2j+1]},  whB likewise for u1.
    ull whA[8], whB[8];
    #pragma unroll
    for (int j = 0; j < 8; ++j) {
        whA[j] = packf2(Wsel[u0 * DD + INDIM + 2 * j], Wsel[u0 * DD + INDIM + 2 * j + 1]);
        whB[j] = packf2(Wsel[u1 * DD + INDIM + 2 * j], Wsel[u1 * DD + INDIM + 2 * j + 1]);
    }

    const float* zp = Z + (size_t)row * NOUT + g * 16 + u0;
    const size_t zstep = (size_t)BB * NOUT;

    float2 zbuf[4];
    #pragma unroll
    for (int i = 0; i < 4; ++i)
        zbuf[i] = *reinterpret_cast<const float2*>(zp + (size_t)i * zstep);
    const float* zpf = zp + 4 * zstep;   // running prefetch pointer (into padding at the end)

    float h0 = 0.f, h1 = 0.f, c0 = 0.f, c1 = 0.f;
    float* outp = out + (size_t)row * HH + u0;

    #pragma unroll 4
    for (int t = 0; t < TT; ++t) {
        float2 zx = zbuf[t & 3];
        zbuf[t & 3] = *reinterpret_cast<const float2*>(zpf);   // no clamp: Z padded
        zpf += zstep;

        // off-chain base terms
        float base0 = zx.x + cth0;
        float base1 = zx.y + cth1;

        // ---- z_h = h . Wh : gather packed pairs, 4 short ffma2 chains ----
        ull hp = packf2(h0, h1);
        ull hj0 = __shfl_sync(FULL, hp, hsrc | 0);
        ull hj1 = __shfl_sync(FULL, hp, hsrc | 1);
        ull hj2 = __shfl_sync(FULL, hp, hsrc | 2);
        ull hj3 = __shfl_sync(FULL, hp, hsrc | 3);
        ull hj4 = __shfl_sync(FULL, hp, hsrc | 4);
        ull hj5 = __shfl_sync(FULL, hp, hsrc | 5);
        ull hj6 = __shfl_sync(FULL, hp, hsrc | 6);
        ull hj7 = __shfl_sync(FULL, hp, hsrc | 7);

        ull a0 = 0ull, a1 = 0ull, b0 = 0ull, b1 = 0ull;
        ffma2(a0, hj0, whA[0]); ffma2(a0, hj1, whA[1]);
        ffma2(a0, hj2, whA[2]); ffma2(a0, hj3, whA[3]);
        ffma2(a1, hj4, whA[4]); ffma2(a1, hj5, whA[5]);
        ffma2(a1, hj6, whA[6]); ffma2(a1, hj7, whA[7]);
        ffma2(b0, hj0, whB[0]); ffma2(b0, hj1, whB[1]);
        ffma2(b0, hj2, whB[2]); ffma2(b0, hj3, whB[3]);
        ffma2(b1, hj4, whB[4]); ffma2(b1, hj5, whB[5]);
        ffma2(b1, hj6, whB[6]); ffma2(b1, hj7, whB[7]);
        float2 fa = unpackf2(addf2(a0, a1));
        float2 fb = unpackf2(addf2(b0, b1));

        float s0 = __sinf((fa.x + fa.y) + base0);
        float s1 = __sinf((fb.x + fb.y) + base1);
        float s01 = s0 + s1;

        // ---- radix-4 segmented scan over 8 lanes (pairwise prefixes) ----
        float v1 = __shfl_up_sync(FULL, s01, 1, 8);
        float v2 = __shfl_up_sync(FULL, s01, 2, 8);
        float v3 = __shfl_up_sync(FULL, s01, 3, 8);
        float t01 = s01 + ((l >= 1) ? v1 : 0.0f);
        float t23 = ((l >= 2) ? v2 : 0.0f) + ((l >= 3) ? v3 : 0.0f);
        float tq  = t01 + t23;                       // sum of up to 4 trailing values
        float v4  = __shfl_up_sync(FULL, tq, 4, 8);
        float p   = tq + ((l >= 4) ? v4 : 0.0f);     // inclusive prefix (pairs)
        float t3  = __shfl_sync(FULL, tq, hsrc | 3); // parallel with round 2
        float t7  = __shfl_sync(FULL, tq, hsrc | 7);
        float tot = t3 + t7;                         // segment total

        float cum1 = p;
        float cum0 = p - s1;
        float q0 = (l == 0) ? (s0 + tot) : cum0;
        float q1 = cum1;

        // ---- branchless activation ----
        float e0 = __expf(q0 * nqs), e1 = __expf(q1 * nqs);
        float sg0 = __fdividef(1.0f, 1.0f + e0);
        float sg1 = __fdividef(1.0f, 1.0f + e1);
        float a0f = fmaf(sc2, sg0, off2);
        float a1f = fmaf(sc2, sg1, off2);

        // ---- gather gates for units (u0,u1) ----
        ull ap = packf2(a0f, a1f);
        ull fp_ = __shfl_sync(FULL, ap, l);
        ull ip_ = __shfl_sync(FULL, ap, 8 | l);
        ull gp_ = __shfl_sync(FULL, ap, 16 | l);
        ull op_ = __shfl_sync(FULL, ap, 24 | l);
        float2 fv = unpackf2(fp_), iv = unpackf2(ip_);
        float2 gv = unpackf2(gp_), ov = unpackf2(op_);

        c0 = fmaf(fv.x, c0, iv.x * gv.x);
        c1 = fmaf(fv.y, c1, iv.y * gv.y);
        // h = o * (1 - u) * rcp(1 + u),  u = exp(-2c)
        float u0e = __expf(-2.0f * c0);
        float u1e = __expf(-2.0f * c1);
        h0 = ov.x * __fdividef(1.0f - u0e, 1.0f + u0e);
        h1 = ov.y * __fdividef(1.0f - u1e, 1.0f + u1e);

        asm volatile(
            "{ .reg .pred p; setp.eq.s32 p, %0, 0;\n\t"
            "@p st.global.v2.f32 [%1], {%2, %3}; }"
            :: "r"(g), "l"(outp), "f"(h0), "f"(h1) : "memory");
        outp += BB * HH;
    }

    if (g == 0) {
        size_t base = (size_t)TT * BB * HH;
        *reinterpret_cast<float2*>(out + base + (size_t)row * HH + u0) = make_float2(h0, h1);
        *reinterpret_cast<float2*>(out + base + (size_t)BB * HH + (size_t)row * HH + u0) = make_float2(c0, c1);
    }
}

extern "C" void kernel_launch(void* const* d_in, const int* in_sizes, int n_in,
                              void* d_out, int out_size) {
    (void)in_sizes; (void)n_in; (void)out_size;
    const float* X   = (const float*)d_in[0];
    const float* Wf  = (const float*)d_in[1];
    const float* bf  = (const float*)d_in[2];
    const float* thf = (const float*)d_in[3];
    const float* Wi  = (const float*)d_in[4];
    const float* bi  = (const float*)d_in[5];
    const float* thi = (const float*)d_in[6];
    const float* Wg  = (const float*)d_in[7];
    const float* bg  = (const float*)d_in[8];
    const float* thg = (const float*)d_in[9];
    const float* Wo  = (const float*)d_in[10];
    const float* bo  = (const float*)d_in[11];
    const float* tho = (const float*)d_in[12];
    float* out = (float*)d_out;

    float* Zp = nullptr;
    cudaGetSymbolAddress((void**)&Zp, g_Z);

    p0_prep<<<NFRAG / 128, 128>>>(Wf, Wi, Wg, Wo);
    p1_mma<<<P1_BLOCKS, 128>>>(X, Zp);
    p2_rec<<<BB / 4, 128>>>(Zp, Wf, bf, thf, Wi, bi, thi,
                            Wg, bg, thg, Wo, bo, tho, out);
}